// round 15
// baseline (speedup 1.0000x reference)
#include <cuda_runtime.h>
#include <stdint.h>
#include <string.h>

#define NIMG 8
#define H 1024
#define W 1024
#define HW (1 << 20)
#define NWORDS (HW / 32)
#define NP 10000
#define PYR_SZ (1 << 21)

// ---------------- scratch (static device globals; no allocation) -------------
// g_pyr layout per image: [0, HW) = sobel s-values (gx^2+gy^2) scratch;
//                         [lvlOff(6), ...) = pyramid levels 6..14. No overlap.
// Atomic scalars are re-zeroed by k_final at the end of every call, so each
// call (first run and every graph replay) starts from zeroed state.
__device__ float g_pyr[NIMG * PYR_SZ];
__device__ uint32_t g_maskbits[NIMG * NWORDS];    // 1 MB bit-packed mask
__device__ unsigned int g_edgemax[NIMG];          // max of s (bits; s >= 0)
__device__ int g_maskcnt[NIMG];
__device__ unsigned int g_maxdiff[NIMG];
__device__ int g_validcnt[NIMG];
__device__ double g_sum_eq[NIMG];                 // direct store (no init needed)
__device__ double g_sum_ne[NIMG];
__device__ float g_tvals[NIMG][NP][4];
__device__ float g_ivals[NIMG][NP][4];
__device__ unsigned char g_validf[NIMG][NP];

struct LaunchParams {
  uint32_t k1[NIMG][2];
  uint32_t k2a[NIMG][2];
  uint32_t k2b[NIMG][2];
  uint32_t pdir[NIMG];
};

// ---------------- Threefry-2x32 (exact JAX, partitionable mode) ---------------
__host__ __device__ __forceinline__ void threefry2x32(uint32_t k0, uint32_t k1,
                                                      uint32_t x0, uint32_t x1,
                                                      uint32_t& o0, uint32_t& o1) {
  uint32_t ks0 = k0, ks1 = k1, ks2 = k0 ^ k1 ^ 0x1BD11BDAu;
  x0 += ks0; x1 += ks1;
#define TF_R(r) { x0 += x1; x1 = (x1 << (r)) | (x1 >> (32 - (r))); x1 ^= x0; }
  TF_R(13) TF_R(15) TF_R(26) TF_R(6)  x0 += ks1; x1 += ks2 + 1u;
  TF_R(17) TF_R(29) TF_R(16) TF_R(24) x0 += ks2; x1 += ks0 + 2u;
  TF_R(13) TF_R(15) TF_R(26) TF_R(6)  x0 += ks0; x1 += ks1 + 3u;
  TF_R(17) TF_R(29) TF_R(16) TF_R(24) x0 += ks1; x1 += ks2 + 4u;
  TF_R(13) TF_R(15) TF_R(26) TF_R(6)  x0 += ks2; x1 += ks0 + 5u;
#undef TF_R
  o0 = x0; o1 = x1;
}
__host__ __device__ __forceinline__ void tf_block(const uint32_t k[2], uint32_t ctr,
                                                  uint32_t& o0, uint32_t& o1) {
  threefry2x32(k[0], k[1], 0u, ctr, o0, o1);
}
__host__ __device__ __forceinline__ uint32_t pbits32(const uint32_t k[2], uint32_t ctr) {
  uint32_t o0, o1; tf_block(k, ctr, o0, o1); return o0 ^ o1;
}

__host__ __device__ __forceinline__ int lvlOff(int b) {
  return (1 << 21) - (1 << (21 - b));
}
__host__ __device__ __forceinline__ int shOff(int b) {   // shared top-tree, b=14..20
  return 128 - (1 << (21 - b));
}

// ---------------- in-register leaf trees (levels <=5 from one mask word) ------
__device__ __forceinline__ float tn1(uint32_t w, int s, float v) {
  return ((w >> s) & 1u) ? v : 0.f;
}
__device__ __forceinline__ float tn2(uint32_t w, int s, float v) {
  return __fadd_rn(tn1(w, s, v), tn1(w, s + 1, v));
}
__device__ __forceinline__ float tn4(uint32_t w, int s, float v) {
  return __fadd_rn(tn2(w, s, v), tn2(w, s + 2, v));
}
__device__ __forceinline__ float tn8(uint32_t w, int s, float v) {
  return __fadd_rn(tn4(w, s, v), tn4(w, s + 4, v));
}
__device__ __forceinline__ float tn16(uint32_t w, int s, float v) {
  return __fadd_rn(tn8(w, s, v), tn8(w, s + 8, v));
}
__device__ __forceinline__ float tn32(uint32_t w, float v) {
  return __fadd_rn(tn16(w, 0, v), tn16(w, 16, v));
}
__device__ __forceinline__ float node_small(const uint32_t* __restrict__ mb,
                                            uint32_t off, int b, float v) {
  uint32_t w = __ldg(&mb[off >> 5]);
  int s = (int)(off & 31u);
  switch (b) {
    case 1: return tn2(w, s, v);
    case 2: return tn4(w, s, v);
    case 3: return tn8(w, s, v);
    case 4: return tn16(w, s, v);
    default: return tn32(w, v);
  }
}
__device__ __forceinline__ float leaf_at(const uint32_t* __restrict__ mb, int i, float v) {
  uint32_t wrd = __ldg(&mb[i >> 5]);
  return ((wrd >> (i & 31)) & 1u) ? v : 0.f;
}

// ---------------- sobel (bit-identical tap order) -----------------------------
__device__ __forceinline__ void sobel_core(float a00, float a01, float a02,
                                           float a10, float a12,
                                           float a20, float a21, float a22,
                                           float& gx, float& gy) {
  gx = __fmul_rn(-1.f, a00);
  gx = __fadd_rn(gx, a02);
  gx = __fadd_rn(gx, __fmul_rn(-2.f, a10));
  gx = __fadd_rn(gx, __fmul_rn(2.f, a12));
  gx = __fadd_rn(gx, __fmul_rn(-1.f, a20));
  gx = __fadd_rn(gx, a22);
  gy = a00;
  gy = __fadd_rn(gy, __fmul_rn(2.f, a01));
  gy = __fadd_rn(gy, a02);
  gy = __fadd_rn(gy, __fmul_rn(-1.f, a20));
  gy = __fadd_rn(gy, __fmul_rn(-2.f, a21));
  gy = __fadd_rn(gy, __fmul_rn(-1.f, a22));
}
__device__ __forceinline__ bool sobel_gxgy(const float* __restrict__ x, int pix,
                                           float& gx, float& gy) {
  int r = pix >> 10, c = pix & (W - 1);
  if (r < 1 || r > H - 2 || c < 1 || c > W - 2) return false;
  sobel_core(x[(r - 1) * W + c - 1], x[(r - 1) * W + c], x[(r - 1) * W + c + 1],
             x[r * W + c - 1], x[r * W + c + 1],
             x[(r + 1) * W + c - 1], x[(r + 1) * W + c], x[(r + 1) * W + c + 1], gx, gy);
  return true;
}
__device__ __forceinline__ float sobel_s(const float* __restrict__ x, int pix) {
  float gx, gy;
  if (!sobel_gxgy(x, pix, gx, gy)) return 0.f;
  return __fadd_rn(__fmul_rn(gx, gx), __fmul_rn(gy, gy));
}

// s = gx^2+gy^2 for 4 consecutive pixels (c0 multiple of 4). (r11-proven codegen)
__device__ __forceinline__ void sobel_s4(const float* __restrict__ x, int r, int c0,
                                         float s[4]) {
  if (r >= 1 && r <= H - 2 && c0 >= 4 && c0 <= W - 8) {
    float up[6], md[6], dn[6];
#pragma unroll
    for (int k = 0; k < 6; k++) {
      up[k] = __ldg(&x[(r - 1) * W + c0 - 1 + k]);
      md[k] = __ldg(&x[r * W + c0 - 1 + k]);
      dn[k] = __ldg(&x[(r + 1) * W + c0 - 1 + k]);
    }
#pragma unroll
    for (int k = 0; k < 4; k++) {
      float gx, gy;
      sobel_core(up[k], up[k + 1], up[k + 2], md[k], md[k + 2],
                 dn[k], dn[k + 1], dn[k + 2], gx, gy);
      s[k] = __fadd_rn(__fmul_rn(gx, gx), __fmul_rn(gy, gy));
    }
  } else {
#pragma unroll
    for (int k = 0; k < 4; k++) s[k] = sobel_s(x, r * W + c0 + k);
  }
}

// ---------------- kernels ----------------------------------------------------
// Pass 1: sobel once; store s; reduce max(s). (max e == sqrtf(max s), monotone)
__global__ void k_edgemax(const float* __restrict__ images) {
  int img = blockIdx.y;
  int t = blockIdx.x * blockDim.x + threadIdx.x;     // 0..HW/4-1
  int pix0 = t * 4;
  int r = pix0 >> 10, c0 = pix0 & (W - 1);
  const float* x = images + (size_t)img * 3 * HW;    // channel 0
  float s[4];
  sobel_s4(x, r, c0, s);
  ((float4*)(g_pyr + (size_t)img * PYR_SZ + pix0))[0] =
      make_float4(s[0], s[1], s[2], s[3]);
  float m = fmaxf(fmaxf(s[0], s[1]), fmaxf(s[2], s[3]));
  unsigned um = __reduce_max_sync(0xFFFFFFFFu, __float_as_uint(m));  // s >= 0
  __shared__ unsigned sm[8];
  if ((threadIdx.x & 31) == 0) sm[threadIdx.x >> 5] = um;
  __syncthreads();
  if (threadIdx.x == 0) {
    unsigned mx = sm[0];
#pragma unroll
    for (int w = 1; w < 8; w++) mx = max(mx, sm[w]);
    atomicMax(&g_edgemax[img], mx);
  }
}

// Pass 2: pure bandwidth — read s, e=sqrtf(s), threshold + strict mask, pack bits.
__global__ void k_mask(const float* __restrict__ tgt, const float* __restrict__ depth) {
  int img = blockIdx.y;
  int t = blockIdx.x * blockDim.x + threadIdx.x;     // 0..HW/16-1
  int p0 = t * 16;
  float emax = sqrtf(__uint_as_float(g_edgemax[img]));  // == max e bitwise
  float thresh = __fmul_rn(0.1f, emax);
  const float* sp = g_pyr + (size_t)img * PYR_SZ;
  uint32_t bits = 0;
#pragma unroll
  for (int q = 0; q < 4; q++) {
    float4 s4 = __ldg((const float4*)(sp + p0 + 4 * q));
    float4 d4 = __ldg((const float4*)(depth + (size_t)img * HW + p0 + 4 * q));
    float4 t4 = __ldg((const float4*)(tgt + (size_t)img * HW + p0 + 4 * q));
    float ss[4] = {s4.x, s4.y, s4.z, s4.w};
    float dd[4] = {d4.x, d4.y, d4.z, d4.w};
    float tg[4] = {t4.x, t4.y, t4.z, t4.w};
#pragma unroll
    for (int k = 0; k < 4; k++) {
      float e = sqrtf(ss[k]);
      bool m = (e >= thresh) && (dd[k] > -0.001f) && (dd[k] < 80.0f) && !(tg[k] == 80.0f);
      if (m) bits |= (1u << (4 * q + k));
    }
  }
  int lane = threadIdx.x & 31;
  uint32_t partner = __shfl_xor_sync(0xFFFFFFFFu, bits, 1);
  if ((lane & 1) == 0)
    g_maskbits[img * NWORDS + (t >> 1)] = bits | (partner << 16);
  int cnt = __reduce_add_sync(0xFFFFFFFFu, __popc(bits));
  __shared__ int cnts[8];
  if (lane == 0) cnts[threadIdx.x >> 5] = cnt;
  __syncthreads();
  if (threadIdx.x == 0) {
    int s = 0;
#pragma unroll
    for (int w = 0; w < 8; w++) s += cnts[w];
    atomicAdd(&g_maskcnt[img], s);
  }
}

// Pyramid levels 6..14 only (same __fadd_rn pairing as reference). (r11-proven)
__global__ void k_pyr() {
  int img = blockIdx.y;
  int cb = blockIdx.x;                                // chunk 0..63 (16384 leaves)
  int t = threadIdx.x;                                // 0..255
  float* gp = g_pyr + (size_t)img * PYR_SZ;
  float S = (float)g_maskcnt[img];
  float v = __fdiv_rn(1.0f, fmaxf(S, 1.0f));
  int wi = cb * 512 + 2 * t;
  uint32_t w0 = g_maskbits[img * NWORDS + wi];
  uint32_t w1 = g_maskbits[img * NWORDS + wi + 1];
  float n6 = __fadd_rn(tn32(w0, v), tn32(w1, v));
  gp[lvlOff(6) + cb * 256 + t] = n6;

  __shared__ float sm[256];
  sm[t] = n6;
  __syncthreads();
#pragma unroll
  for (int b = 7; b <= 14; b++) {
    int n = 1 << (14 - b);
    float xv = 0.f;
    if (t < n) {
      xv = __fadd_rn(sm[2 * t], sm[2 * t + 1]);
      gp[lvlOff(b) + cb * n + t] = xv;
    }
    __syncthreads();
    if (t < n) sm[t] = xv;
    __syncthreads();
  }
}

// Generic cumsum[m-1] via aligned-block decomposition (reference association).
__device__ __forceinline__ float cumsum_generic(const float* __restrict__ gp,
                                                const uint32_t* __restrict__ mb,
                                                const float* __restrict__ sh,
                                                float v, uint32_t m) {
  float acc = 0.f;
  uint32_t off = 0;
#pragma unroll
  for (int b = 20; b >= 14; b--) {
    if ((m >> b) & 1u) {
      acc = __fadd_rn(acc, sh[shOff(b) + (off >> b)]);
      off += (1u << b);
    }
  }
#pragma unroll
  for (int b = 13; b >= 6; b--) {
    if ((m >> b) & 1u) {
      acc = __fadd_rn(acc, __ldg(&gp[lvlOff(b) + (off >> b)]));
      off += (1u << b);
    }
  }
#pragma unroll
  for (int b = 5; b >= 1; b--) {
    if ((m >> b) & 1u) {
      acc = __fadd_rn(acc, node_small(mb, off, b, v));
      off += (1u << b);
    }
  }
  if (m & 1u) acc = __fadd_rn(acc, leaf_at(mb, (int)off, v));
  return acc;
}

__global__ void k_sample(LaunchParams P, const float* __restrict__ inp,
                         const float* __restrict__ tgt,
                         const float* __restrict__ images) {
  int img = blockIdx.y;
  const float* gp = g_pyr + (size_t)img * PYR_SZ;
  const uint32_t* mb = g_maskbits + img * NWORDS;

  // Build top tree (levels 14..20, 127 floats) in shared from level 14.
  __shared__ float sh[128];
  if (threadIdx.x < 64) sh[threadIdx.x] = gp[lvlOff(14) + threadIdx.x];
  __syncthreads();
#pragma unroll
  for (int b = 15; b <= 20; b++) {
    int n = 1 << (20 - b);
    if ((int)threadIdx.x < n)
      sh[shOff(b) + threadIdx.x] =
          __fadd_rn(sh[shOff(b - 1) + 2 * threadIdx.x], sh[shOff(b - 1) + 2 * threadIdx.x + 1]);
    __syncthreads();
  }

  int j = blockIdx.x * blockDim.x + threadIdx.x;
  if (j >= NP) return;
  float S = (float)g_maskcnt[img];
  float v = __fdiv_rn(1.0f, fmaxf(S, 1.0f));

  uint32_t ub = pbits32(P.k1[img], (uint32_t)j);
  float u = __uint_as_float((ub >> 9) | 0x3F800000u) - 1.0f;
  float T = sh[126];
  float r = __fmul_rn(T, __fsub_rn(1.0f, u));

  // searchsorted 'scan': incremental descent b=19..1, then 2 generic evals.
  int low = 0;
  float A = 0.f;
#pragma unroll 1
  for (int b = 19; b >= 1; b--) {
    int mid = low + (1 << b);
    float node;
    if (b >= 14)      node = sh[shOff(b) + (low >> b)];
    else if (b >= 6)  node = __ldg(&gp[lvlOff(b) + (low >> b)]);
    else              node = node_small(mb, (uint32_t)low, b, v);
    float t1 = __fadd_rn(A, node);
    float acc = __fadd_rn(t1, leaf_at(mb, mid, v));
    if (!(r <= acc)) { A = t1; low = mid; }
  }
  {
    float acc = cumsum_generic(gp, mb, sh, v, (uint32_t)low + 2u);
    if (!(r <= acc)) low = low + 1;
  }
  int idx;
  {
    float acc = cumsum_generic(gp, mb, sh, v, (uint32_t)low + 1u);
    idx = (r <= acc) ? low : low + 1;
  }
  if (idx > HW - 1) idx = HW - 1;

  int shc = idx >> 10, sw = idx & (W - 1);
  float th = 0.f;
  {
    float gx, gy;
    const float* x = images + (size_t)img * 3 * HW;
    if (sobel_gxgy(x, idx, gx, gy)) th = atan2f(gy, gx);
  }
  float c0 = cosf(th), s0 = sinf(th);
  float xx = __fadd_rn(__fadd_rn(th, 1.5707964f), 3.1415927f);
  float tm = fmodf(xx, 6.2831855f);
  if (tm != 0.0f && tm < 0.0f) tm = __fadd_rn(tm, 6.2831855f);
  float th2 = __fsub_rn(tm, 3.1415927f);
  float s2 = sinf(th2), c2 = cosf(th2);
  bool pd = P.pdir[img] != 0;

  int rows[4], cols[4];
  bool ok = true;
#pragma unroll
  for (int i = 0; i < 4; i++) {
    uint32_t f = (uint32_t)(i * NP + j);
    uint32_t hb = pbits32(P.k2a[img], f);
    uint32_t lb = pbits32(P.k2b[img], f);
    uint32_t offr = ((hb % 29u) * 16u + (lb % 29u)) % 29u;
    float d = (float)(2u + offr);
    if (i < 2) d = -d;
    int col, row;
    if (pd) {
      col = sw + (int)rintf(__fmul_rn(d, c0));
      row = shc + (int)rintf(__fmul_rn(d, s0));
    } else {
      col = sw + (int)rintf(__fmul_rn(d, s2));
      row = shc + (int)rintf(__fmul_rn(d, c2));
    }
    ok = ok && (col >= 0) && (col <= W - 1) && (row >= 0) && (row <= H - 1);
    cols[i] = min(max(col, 0), W - 1);
    rows[i] = min(max(row, 0), H - 1);
  }
  const float* ip = inp + (size_t)img * HW;
  const float* tp = tgt + (size_t)img * HW;
  float tv[4];
#pragma unroll
  for (int i = 0; i < 4; i++) {
    int p = rows[i] * W + cols[i];
    float ivv = __ldg(&ip[p]);
    tv[i] = __ldg(&tp[p]);
    g_ivals[img][j][i] = ivv;
    g_tvals[img][j][i] = tv[i];
  }
  g_validf[img][j] = ok ? 1 : 0;
  if (ok) {
    float m0 = fabsf(__fsub_rn(tv[0], tv[1]));
    float m1 = fabsf(__fsub_rn(tv[1], tv[2]));
    float m2 = fabsf(__fsub_rn(tv[2], tv[3]));
    float mm = fmaxf(m0, fmaxf(m1, m2));
    atomicMax(&g_maxdiff[img], __float_as_uint(mm));
    atomicAdd(&g_validcnt[img], 1);
  }
}

// One block per image: full reduction, direct store (no atomics, no init needed).
__global__ void k_loss() {
  int img = blockIdx.x;
  double se = 0.0, sn = 0.0;
  float md = __uint_as_float(g_maxdiff[img]);
  float denom = __fadd_rn(md, 1e-6f);
  const float CHI = (float)(1.0 + 0.03);
  const float CLO = (float)(1.0 / (1.0 + 0.03));
  for (int j = threadIdx.x; j < NP; j += blockDim.x) {
    float vm = g_validf[img][j] ? 1.0f : 0.0f;
#pragma unroll
    for (int k = 0; k < 3; k++) {
      float tA = g_tvals[img][j][k], tB = g_tvals[img][j][k + 1];
      float iA = g_ivals[img][j][k], iB = g_ivals[img][j][k + 1];
      float ratio = __fdiv_rn(__fadd_rn(tA, 1e-6f), __fadd_rn(tB, 1e-6f));
      float ad = fabsf(__fsub_rn(tA, tB));
      float tw = expf(__fdiv_rn(ad, denom));
      bool eqb = (ratio < CHI) && (ratio > CLO);
      float eqf = eqb ? 1.0f : 0.0f;
      float label = (ratio >= CHI) ? 1.0f : ((ratio <= CLO) ? -1.0f : 0.0f);
      float dd = __fsub_rn(iA, iB);
      float el = __fmul_rn(__fdiv_rn(__fmul_rn(dd, dd), tw), eqf);
      float z = __fmul_rn(__fsub_rn(iB, iA), label);
      float ue = __fmul_rn(log1pf(expf(z)), __fsub_rn(1.0f, eqf));
      se += (double)__fmul_rn(el, vm);
      sn += (double)__fmul_rn(ue, vm);
    }
  }
  __shared__ double sh_se[256];
  __shared__ double sh_sn[256];
  sh_se[threadIdx.x] = se; sh_sn[threadIdx.x] = sn;
  __syncthreads();
  for (int s = blockDim.x / 2; s > 0; s >>= 1) {
    if ((int)threadIdx.x < s) {
      sh_se[threadIdx.x] += sh_se[threadIdx.x + s];
      sh_sn[threadIdx.x] += sh_sn[threadIdx.x + s];
    }
    __syncthreads();
  }
  if (threadIdx.x == 0) {
    g_sum_eq[img] = sh_se[0];
    g_sum_ne[img] = sh_sn[0];
  }
}

// Output + re-zero accumulators for the next call (keeps replay invariant).
__global__ void k_final(float* out, int out_size) {
  if (threadIdx.x == 0 && blockIdx.x == 0) {
    float ls = 0.f, cs = 0.f;
    for (int i = 0; i < NIMG; i++) {
      float nv = 3.0f * (float)g_validcnt[i];
      float cnt = fmaxf(nv, 1.0f);
      float li = (float)(g_sum_eq[i] / (double)cnt + g_sum_ne[i] / (double)cnt);
      ls += li; cs += nv;
    }
    if (out_size >= 1) out[0] = ls / 8.0f;
    if (out_size >= 2) out[1] = cs / 8.0f;
    for (int i = 0; i < NIMG; i++) {
      g_edgemax[i] = 0u; g_maskcnt[i] = 0; g_maxdiff[i] = 0u; g_validcnt[i] = 0;
    }
  }
}

// ---------------- host --------------------------------------------------------
extern "C" void kernel_launch(void* const* d_in, const int* in_sizes, int n_in,
                              void* d_out, int out_size) {
  const float* inputs  = (const float*)d_in[0];
  const float* targets = (const float*)d_in[1];
  const float* images  = (const float*)d_in[2];
  const float* depth   = (const float*)d_in[3];
  float* out = (float*)d_out;
  (void)in_sizes; (void)n_in;

  LaunchParams P;
  uint32_t root[2] = {0u, 42u};
  for (int i = 0; i < NIMG; i++) {
    uint32_t ik[2];
    tf_block(root, (uint32_t)i, ik[0], ik[1]);
    uint32_t k1[2], k2[2], k3[2];
    tf_block(ik, 0u, k1[0], k1[1]);
    tf_block(ik, 1u, k2[0], k2[1]);
    tf_block(ik, 2u, k3[0], k3[1]);
    P.k1[i][0] = k1[0]; P.k1[i][1] = k1[1];
    tf_block(k2, 0u, P.k2a[i][0], P.k2a[i][1]);
    tf_block(k2, 1u, P.k2b[i][0], P.k2b[i][1]);
    uint32_t bits = pbits32(k3, 0u);
    uint32_t fb = (bits >> 9) | 0x3F800000u;
    float uu; memcpy(&uu, &fb, 4); uu -= 1.0f;
    P.pdir[i] = (uu < 0.5f) ? 1u : 0u;
  }

  dim3 gs4(HW / 4 / 256, NIMG);
  k_edgemax<<<gs4, 256>>>(images);
  dim3 gs16(HW / 16 / 256, NIMG);
  k_mask<<<gs16, 256>>>(targets, depth);
  k_pyr<<<dim3(64, NIMG), 256>>>();
  dim3 gsamp((NP + 127) / 128, NIMG);
  k_sample<<<gsamp, 128>>>(P, inputs, targets, images);
  k_loss<<<NIMG, 256>>>();
  k_final<<<1, 1>>>(out, out_size);
}

// round 16
// speedup vs baseline: 1.6024x; 1.6024x over previous
#include <cuda_runtime.h>
#include <stdint.h>
#include <string.h>

#define NIMG 8
#define H 1024
#define W 1024
#define HW (1 << 20)
#define NWORDS (HW / 32)
#define NP 10000
#define PYR_SZ (1 << 21)

// ---------------- scratch (static device globals; no allocation) -------------
// g_pyr layout per image: [0, HW) = sobel s-values (gx^2+gy^2) scratch;
//                         [lvlOff(6), ...) = pyramid levels 6..14. No overlap.
// All accumulator scalars are re-zeroed by k_final at the end of every call,
// so each call (first run and every graph replay) starts from zeroed state.
__device__ float g_pyr[NIMG * PYR_SZ];
__device__ uint32_t g_maskbits[NIMG * NWORDS];    // 1 MB bit-packed mask
__device__ unsigned int g_edgemax[NIMG];          // max of s (bits; s >= 0)
__device__ int g_maskcnt[NIMG];
__device__ unsigned int g_maxdiff[NIMG];
__device__ int g_validcnt[NIMG];
__device__ double g_sum_eq[NIMG];
__device__ double g_sum_ne[NIMG];
__device__ float g_tvals[NIMG][NP][4];
__device__ float g_ivals[NIMG][NP][4];
__device__ unsigned char g_validf[NIMG][NP];

struct LaunchParams {
  uint32_t k1[NIMG][2];
  uint32_t k2a[NIMG][2];
  uint32_t k2b[NIMG][2];
  uint32_t pdir[NIMG];
};

// ---------------- Threefry-2x32 (exact JAX, partitionable mode) ---------------
__host__ __device__ __forceinline__ void threefry2x32(uint32_t k0, uint32_t k1,
                                                      uint32_t x0, uint32_t x1,
                                                      uint32_t& o0, uint32_t& o1) {
  uint32_t ks0 = k0, ks1 = k1, ks2 = k0 ^ k1 ^ 0x1BD11BDAu;
  x0 += ks0; x1 += ks1;
#define TF_R(r) { x0 += x1; x1 = (x1 << (r)) | (x1 >> (32 - (r))); x1 ^= x0; }
  TF_R(13) TF_R(15) TF_R(26) TF_R(6)  x0 += ks1; x1 += ks2 + 1u;
  TF_R(17) TF_R(29) TF_R(16) TF_R(24) x0 += ks2; x1 += ks0 + 2u;
  TF_R(13) TF_R(15) TF_R(26) TF_R(6)  x0 += ks0; x1 += ks1 + 3u;
  TF_R(17) TF_R(29) TF_R(16) TF_R(24) x0 += ks1; x1 += ks2 + 4u;
  TF_R(13) TF_R(15) TF_R(26) TF_R(6)  x0 += ks2; x1 += ks0 + 5u;
#undef TF_R
  o0 = x0; o1 = x1;
}
__host__ __device__ __forceinline__ void tf_block(const uint32_t k[2], uint32_t ctr,
                                                  uint32_t& o0, uint32_t& o1) {
  threefry2x32(k[0], k[1], 0u, ctr, o0, o1);
}
__host__ __device__ __forceinline__ uint32_t pbits32(const uint32_t k[2], uint32_t ctr) {
  uint32_t o0, o1; tf_block(k, ctr, o0, o1); return o0 ^ o1;
}

__host__ __device__ __forceinline__ int lvlOff(int b) {
  return (1 << 21) - (1 << (21 - b));
}
__host__ __device__ __forceinline__ int shOff(int b) {   // shared top-tree, b=14..20
  return 128 - (1 << (21 - b));
}

// ---------------- in-register leaf trees (levels <=5 from one mask word) ------
__device__ __forceinline__ float tn1(uint32_t w, int s, float v) {
  return ((w >> s) & 1u) ? v : 0.f;
}
__device__ __forceinline__ float tn2(uint32_t w, int s, float v) {
  return __fadd_rn(tn1(w, s, v), tn1(w, s + 1, v));
}
__device__ __forceinline__ float tn4(uint32_t w, int s, float v) {
  return __fadd_rn(tn2(w, s, v), tn2(w, s + 2, v));
}
__device__ __forceinline__ float tn8(uint32_t w, int s, float v) {
  return __fadd_rn(tn4(w, s, v), tn4(w, s + 4, v));
}
__device__ __forceinline__ float tn16(uint32_t w, int s, float v) {
  return __fadd_rn(tn8(w, s, v), tn8(w, s + 8, v));
}
__device__ __forceinline__ float tn32(uint32_t w, float v) {
  return __fadd_rn(tn16(w, 0, v), tn16(w, 16, v));
}
__device__ __forceinline__ float node_small(const uint32_t* __restrict__ mb,
                                            uint32_t off, int b, float v) {
  uint32_t w = __ldg(&mb[off >> 5]);
  int s = (int)(off & 31u);
  switch (b) {
    case 1: return tn2(w, s, v);
    case 2: return tn4(w, s, v);
    case 3: return tn8(w, s, v);
    case 4: return tn16(w, s, v);
    default: return tn32(w, v);
  }
}
__device__ __forceinline__ float leaf_at(const uint32_t* __restrict__ mb, int i, float v) {
  uint32_t wrd = __ldg(&mb[i >> 5]);
  return ((wrd >> (i & 31)) & 1u) ? v : 0.f;
}

// ---------------- sobel (bit-identical tap order) -----------------------------
__device__ __forceinline__ void sobel_core(float a00, float a01, float a02,
                                           float a10, float a12,
                                           float a20, float a21, float a22,
                                           float& gx, float& gy) {
  gx = __fmul_rn(-1.f, a00);
  gx = __fadd_rn(gx, a02);
  gx = __fadd_rn(gx, __fmul_rn(-2.f, a10));
  gx = __fadd_rn(gx, __fmul_rn(2.f, a12));
  gx = __fadd_rn(gx, __fmul_rn(-1.f, a20));
  gx = __fadd_rn(gx, a22);
  gy = a00;
  gy = __fadd_rn(gy, __fmul_rn(2.f, a01));
  gy = __fadd_rn(gy, a02);
  gy = __fadd_rn(gy, __fmul_rn(-1.f, a20));
  gy = __fadd_rn(gy, __fmul_rn(-2.f, a21));
  gy = __fadd_rn(gy, __fmul_rn(-1.f, a22));
}
__device__ __forceinline__ bool sobel_gxgy(const float* __restrict__ x, int pix,
                                           float& gx, float& gy) {
  int r = pix >> 10, c = pix & (W - 1);
  if (r < 1 || r > H - 2 || c < 1 || c > W - 2) return false;
  sobel_core(x[(r - 1) * W + c - 1], x[(r - 1) * W + c], x[(r - 1) * W + c + 1],
             x[r * W + c - 1], x[r * W + c + 1],
             x[(r + 1) * W + c - 1], x[(r + 1) * W + c], x[(r + 1) * W + c + 1], gx, gy);
  return true;
}
__device__ __forceinline__ float sobel_s(const float* __restrict__ x, int pix) {
  float gx, gy;
  if (!sobel_gxgy(x, pix, gx, gy)) return 0.f;
  return __fadd_rn(__fmul_rn(gx, gx), __fmul_rn(gy, gy));
}

// s = gx^2+gy^2 for 4 consecutive pixels (c0 multiple of 4). (r11-proven codegen)
__device__ __forceinline__ void sobel_s4(const float* __restrict__ x, int r, int c0,
                                         float s[4]) {
  if (r >= 1 && r <= H - 2 && c0 >= 4 && c0 <= W - 8) {
    float up[6], md[6], dn[6];
#pragma unroll
    for (int k = 0; k < 6; k++) {
      up[k] = __ldg(&x[(r - 1) * W + c0 - 1 + k]);
      md[k] = __ldg(&x[r * W + c0 - 1 + k]);
      dn[k] = __ldg(&x[(r + 1) * W + c0 - 1 + k]);
    }
#pragma unroll
    for (int k = 0; k < 4; k++) {
      float gx, gy;
      sobel_core(up[k], up[k + 1], up[k + 2], md[k], md[k + 2],
                 dn[k], dn[k + 1], dn[k + 2], gx, gy);
      s[k] = __fadd_rn(__fmul_rn(gx, gx), __fmul_rn(gy, gy));
    }
  } else {
#pragma unroll
    for (int k = 0; k < 4; k++) s[k] = sobel_s(x, r * W + c0 + k);
  }
}

// ---------------- kernels ----------------------------------------------------
// Pass 1: sobel once; store s; reduce max(s). (max e == sqrtf(max s), monotone)
__global__ void k_edgemax(const float* __restrict__ images) {
  int img = blockIdx.y;
  int t = blockIdx.x * blockDim.x + threadIdx.x;     // 0..HW/4-1
  int pix0 = t * 4;
  int r = pix0 >> 10, c0 = pix0 & (W - 1);
  const float* x = images + (size_t)img * 3 * HW;    // channel 0
  float s[4];
  sobel_s4(x, r, c0, s);
  ((float4*)(g_pyr + (size_t)img * PYR_SZ + pix0))[0] =
      make_float4(s[0], s[1], s[2], s[3]);
  float m = fmaxf(fmaxf(s[0], s[1]), fmaxf(s[2], s[3]));
  unsigned um = __reduce_max_sync(0xFFFFFFFFu, __float_as_uint(m));  // s >= 0
  __shared__ unsigned sm[8];
  if ((threadIdx.x & 31) == 0) sm[threadIdx.x >> 5] = um;
  __syncthreads();
  if (threadIdx.x == 0) {
    unsigned mx = sm[0];
#pragma unroll
    for (int w = 1; w < 8; w++) mx = max(mx, sm[w]);
    atomicMax(&g_edgemax[img], mx);
  }
}

// Pass 2: pure bandwidth — read s, e=sqrtf(s), threshold + strict mask, pack bits.
__global__ void k_mask(const float* __restrict__ tgt, const float* __restrict__ depth) {
  int img = blockIdx.y;
  int t = blockIdx.x * blockDim.x + threadIdx.x;     // 0..HW/16-1
  int p0 = t * 16;
  float emax = sqrtf(__uint_as_float(g_edgemax[img]));  // == max e bitwise
  float thresh = __fmul_rn(0.1f, emax);
  const float* sp = g_pyr + (size_t)img * PYR_SZ;
  uint32_t bits = 0;
#pragma unroll
  for (int q = 0; q < 4; q++) {
    float4 s4 = __ldg((const float4*)(sp + p0 + 4 * q));
    float4 d4 = __ldg((const float4*)(depth + (size_t)img * HW + p0 + 4 * q));
    float4 t4 = __ldg((const float4*)(tgt + (size_t)img * HW + p0 + 4 * q));
    float ss[4] = {s4.x, s4.y, s4.z, s4.w};
    float dd[4] = {d4.x, d4.y, d4.z, d4.w};
    float tg[4] = {t4.x, t4.y, t4.z, t4.w};
#pragma unroll
    for (int k = 0; k < 4; k++) {
      float e = sqrtf(ss[k]);
      bool m = (e >= thresh) && (dd[k] > -0.001f) && (dd[k] < 80.0f) && !(tg[k] == 80.0f);
      if (m) bits |= (1u << (4 * q + k));
    }
  }
  int lane = threadIdx.x & 31;
  uint32_t partner = __shfl_xor_sync(0xFFFFFFFFu, bits, 1);
  if ((lane & 1) == 0)
    g_maskbits[img * NWORDS + (t >> 1)] = bits | (partner << 16);
  int cnt = __reduce_add_sync(0xFFFFFFFFu, __popc(bits));
  __shared__ int cnts[8];
  if (lane == 0) cnts[threadIdx.x >> 5] = cnt;
  __syncthreads();
  if (threadIdx.x == 0) {
    int s = 0;
#pragma unroll
    for (int w = 0; w < 8; w++) s += cnts[w];
    atomicAdd(&g_maskcnt[img], s);
  }
}

// Pyramid levels 6..14 only (same __fadd_rn pairing as reference). (r11-proven)
__global__ void k_pyr() {
  int img = blockIdx.y;
  int cb = blockIdx.x;                                // chunk 0..63 (16384 leaves)
  int t = threadIdx.x;                                // 0..255
  float* gp = g_pyr + (size_t)img * PYR_SZ;
  float S = (float)g_maskcnt[img];
  float v = __fdiv_rn(1.0f, fmaxf(S, 1.0f));
  int wi = cb * 512 + 2 * t;
  uint32_t w0 = g_maskbits[img * NWORDS + wi];
  uint32_t w1 = g_maskbits[img * NWORDS + wi + 1];
  float n6 = __fadd_rn(tn32(w0, v), tn32(w1, v));
  gp[lvlOff(6) + cb * 256 + t] = n6;

  __shared__ float sm[256];
  sm[t] = n6;
  __syncthreads();
#pragma unroll
  for (int b = 7; b <= 14; b++) {
    int n = 1 << (14 - b);
    float xv = 0.f;
    if (t < n) {
      xv = __fadd_rn(sm[2 * t], sm[2 * t + 1]);
      gp[lvlOff(b) + cb * n + t] = xv;
    }
    __syncthreads();
    if (t < n) sm[t] = xv;
    __syncthreads();
  }
}

// Generic cumsum[m-1] via aligned-block decomposition (reference association).
__device__ __forceinline__ float cumsum_generic(const float* __restrict__ gp,
                                                const uint32_t* __restrict__ mb,
                                                const float* __restrict__ sh,
                                                float v, uint32_t m) {
  float acc = 0.f;
  uint32_t off = 0;
#pragma unroll
  for (int b = 20; b >= 14; b--) {
    if ((m >> b) & 1u) {
      acc = __fadd_rn(acc, sh[shOff(b) + (off >> b)]);
      off += (1u << b);
    }
  }
#pragma unroll
  for (int b = 13; b >= 6; b--) {
    if ((m >> b) & 1u) {
      acc = __fadd_rn(acc, __ldg(&gp[lvlOff(b) + (off >> b)]));
      off += (1u << b);
    }
  }
#pragma unroll
  for (int b = 5; b >= 1; b--) {
    if ((m >> b) & 1u) {
      acc = __fadd_rn(acc, node_small(mb, off, b, v));
      off += (1u << b);
    }
  }
  if (m & 1u) acc = __fadd_rn(acc, leaf_at(mb, (int)off, v));
  return acc;
}

__global__ void k_sample(LaunchParams P, const float* __restrict__ inp,
                         const float* __restrict__ tgt,
                         const float* __restrict__ images) {
  int img = blockIdx.y;
  const float* gp = g_pyr + (size_t)img * PYR_SZ;
  const uint32_t* mb = g_maskbits + img * NWORDS;

  // Build top tree (levels 14..20, 127 floats) in shared from level 14.
  __shared__ float sh[128];
  if (threadIdx.x < 64) sh[threadIdx.x] = gp[lvlOff(14) + threadIdx.x];
  __syncthreads();
#pragma unroll
  for (int b = 15; b <= 20; b++) {
    int n = 1 << (20 - b);
    if ((int)threadIdx.x < n)
      sh[shOff(b) + threadIdx.x] =
          __fadd_rn(sh[shOff(b - 1) + 2 * threadIdx.x], sh[shOff(b - 1) + 2 * threadIdx.x + 1]);
    __syncthreads();
  }

  int j = blockIdx.x * blockDim.x + threadIdx.x;
  if (j >= NP) return;
  float S = (float)g_maskcnt[img];
  float v = __fdiv_rn(1.0f, fmaxf(S, 1.0f));

  uint32_t ub = pbits32(P.k1[img], (uint32_t)j);
  float u = __uint_as_float((ub >> 9) | 0x3F800000u) - 1.0f;
  float T = sh[126];
  float r = __fmul_rn(T, __fsub_rn(1.0f, u));

  // searchsorted 'scan': incremental descent b=19..1, then 2 generic evals.
  int low = 0;
  float A = 0.f;
#pragma unroll 1
  for (int b = 19; b >= 1; b--) {
    int mid = low + (1 << b);
    float node;
    if (b >= 14)      node = sh[shOff(b) + (low >> b)];
    else if (b >= 6)  node = __ldg(&gp[lvlOff(b) + (low >> b)]);
    else              node = node_small(mb, (uint32_t)low, b, v);
    float t1 = __fadd_rn(A, node);
    float acc = __fadd_rn(t1, leaf_at(mb, mid, v));
    if (!(r <= acc)) { A = t1; low = mid; }
  }
  {
    float acc = cumsum_generic(gp, mb, sh, v, (uint32_t)low + 2u);
    if (!(r <= acc)) low = low + 1;
  }
  int idx;
  {
    float acc = cumsum_generic(gp, mb, sh, v, (uint32_t)low + 1u);
    idx = (r <= acc) ? low : low + 1;
  }
  if (idx > HW - 1) idx = HW - 1;

  int shc = idx >> 10, sw = idx & (W - 1);
  float th = 0.f;
  {
    float gx, gy;
    const float* x = images + (size_t)img * 3 * HW;
    if (sobel_gxgy(x, idx, gx, gy)) th = atan2f(gy, gx);
  }
  float c0 = cosf(th), s0 = sinf(th);
  float xx = __fadd_rn(__fadd_rn(th, 1.5707964f), 3.1415927f);
  float tm = fmodf(xx, 6.2831855f);
  if (tm != 0.0f && tm < 0.0f) tm = __fadd_rn(tm, 6.2831855f);
  float th2 = __fsub_rn(tm, 3.1415927f);
  float s2 = sinf(th2), c2 = cosf(th2);
  bool pd = P.pdir[img] != 0;

  int rows[4], cols[4];
  bool ok = true;
#pragma unroll
  for (int i = 0; i < 4; i++) {
    uint32_t f = (uint32_t)(i * NP + j);
    uint32_t hb = pbits32(P.k2a[img], f);
    uint32_t lb = pbits32(P.k2b[img], f);
    uint32_t offr = ((hb % 29u) * 16u + (lb % 29u)) % 29u;
    float d = (float)(2u + offr);
    if (i < 2) d = -d;
    int col, row;
    if (pd) {
      col = sw + (int)rintf(__fmul_rn(d, c0));
      row = shc + (int)rintf(__fmul_rn(d, s0));
    } else {
      col = sw + (int)rintf(__fmul_rn(d, s2));
      row = shc + (int)rintf(__fmul_rn(d, c2));
    }
    ok = ok && (col >= 0) && (col <= W - 1) && (row >= 0) && (row <= H - 1);
    cols[i] = min(max(col, 0), W - 1);
    rows[i] = min(max(row, 0), H - 1);
  }
  const float* ip = inp + (size_t)img * HW;
  const float* tp = tgt + (size_t)img * HW;
  float tv[4];
#pragma unroll
  for (int i = 0; i < 4; i++) {
    int p = rows[i] * W + cols[i];
    float ivv = __ldg(&ip[p]);
    tv[i] = __ldg(&tp[p]);
    g_ivals[img][j][i] = ivv;
    g_tvals[img][j][i] = tv[i];
  }
  g_validf[img][j] = ok ? 1 : 0;
  if (ok) {
    float m0 = fabsf(__fsub_rn(tv[0], tv[1]));
    float m1 = fabsf(__fsub_rn(tv[1], tv[2]));
    float m2 = fabsf(__fsub_rn(tv[2], tv[3]));
    float mm = fmaxf(m0, fmaxf(m1, m2));
    atomicMax(&g_maxdiff[img], __float_as_uint(mm));
    atomicAdd(&g_validcnt[img], 1);
  }
}

// Wide grid (632 blocks): MUFU-heavy work spread across all SMs; atomic reduce.
__global__ void k_loss() {
  int j = blockIdx.x * blockDim.x + threadIdx.x;
  int img = blockIdx.y;
  double se = 0.0, sn = 0.0;
  if (j < NP) {
    float md = __uint_as_float(g_maxdiff[img]);
    float denom = __fadd_rn(md, 1e-6f);
    float vm = g_validf[img][j] ? 1.0f : 0.0f;
    const float CHI = (float)(1.0 + 0.03);
    const float CLO = (float)(1.0 / (1.0 + 0.03));
#pragma unroll
    for (int k = 0; k < 3; k++) {
      float tA = g_tvals[img][j][k], tB = g_tvals[img][j][k + 1];
      float iA = g_ivals[img][j][k], iB = g_ivals[img][j][k + 1];
      float ratio = __fdiv_rn(__fadd_rn(tA, 1e-6f), __fadd_rn(tB, 1e-6f));
      float ad = fabsf(__fsub_rn(tA, tB));
      float tw = expf(__fdiv_rn(ad, denom));
      bool eqb = (ratio < CHI) && (ratio > CLO);
      float eqf = eqb ? 1.0f : 0.0f;
      float label = (ratio >= CHI) ? 1.0f : ((ratio <= CLO) ? -1.0f : 0.0f);
      float dd = __fsub_rn(iA, iB);
      float el = __fmul_rn(__fdiv_rn(__fmul_rn(dd, dd), tw), eqf);
      float z = __fmul_rn(__fsub_rn(iB, iA), label);
      float ue = __fmul_rn(log1pf(expf(z)), __fsub_rn(1.0f, eqf));
      se += (double)__fmul_rn(el, vm);
      sn += (double)__fmul_rn(ue, vm);
    }
  }
  __shared__ double sh_se[128];
  __shared__ double sh_sn[128];
  sh_se[threadIdx.x] = se; sh_sn[threadIdx.x] = sn;
  __syncthreads();
  for (int s = blockDim.x / 2; s > 0; s >>= 1) {
    if ((int)threadIdx.x < s) {
      sh_se[threadIdx.x] += sh_se[threadIdx.x + s];
      sh_sn[threadIdx.x] += sh_sn[threadIdx.x + s];
    }
    __syncthreads();
  }
  if (threadIdx.x == 0) {
    atomicAdd(&g_sum_eq[img], sh_se[0]);
    atomicAdd(&g_sum_ne[img], sh_sn[0]);
  }
}

// Output + re-zero ALL accumulators for the next call (replay invariant).
__global__ void k_final(float* out, int out_size) {
  if (threadIdx.x == 0 && blockIdx.x == 0) {
    float ls = 0.f, cs = 0.f;
    for (int i = 0; i < NIMG; i++) {
      float nv = 3.0f * (float)g_validcnt[i];
      float cnt = fmaxf(nv, 1.0f);
      float li = (float)(g_sum_eq[i] / (double)cnt + g_sum_ne[i] / (double)cnt);
      ls += li; cs += nv;
    }
    if (out_size >= 1) out[0] = ls / 8.0f;
    if (out_size >= 2) out[1] = cs / 8.0f;
    for (int i = 0; i < NIMG; i++) {
      g_edgemax[i] = 0u; g_maskcnt[i] = 0; g_maxdiff[i] = 0u; g_validcnt[i] = 0;
      g_sum_eq[i] = 0.0; g_sum_ne[i] = 0.0;
    }
  }
}

// ---------------- host --------------------------------------------------------
extern "C" void kernel_launch(void* const* d_in, const int* in_sizes, int n_in,
                              void* d_out, int out_size) {
  const float* inputs  = (const float*)d_in[0];
  const float* targets = (const float*)d_in[1];
  const float* images  = (const float*)d_in[2];
  const float* depth   = (const float*)d_in[3];
  float* out = (float*)d_out;
  (void)in_sizes; (void)n_in;

  LaunchParams P;
  uint32_t root[2] = {0u, 42u};
  for (int i = 0; i < NIMG; i++) {
    uint32_t ik[2];
    tf_block(root, (uint32_t)i, ik[0], ik[1]);
    uint32_t k1[2], k2[2], k3[2];
    tf_block(ik, 0u, k1[0], k1[1]);
    tf_block(ik, 1u, k2[0], k2[1]);
    tf_block(ik, 2u, k3[0], k3[1]);
    P.k1[i][0] = k1[0]; P.k1[i][1] = k1[1];
    tf_block(k2, 0u, P.k2a[i][0], P.k2a[i][1]);
    tf_block(k2, 1u, P.k2b[i][0], P.k2b[i][1]);
    uint32_t bits = pbits32(k3, 0u);
    uint32_t fb = (bits >> 9) | 0x3F800000u;
    float uu; memcpy(&uu, &fb, 4); uu -= 1.0f;
    P.pdir[i] = (uu < 0.5f) ? 1u : 0u;
  }

  dim3 gs4(HW / 4 / 256, NIMG);
  k_edgemax<<<gs4, 256>>>(images);
  dim3 gs16(HW / 16 / 256, NIMG);
  k_mask<<<gs16, 256>>>(targets, depth);
  k_pyr<<<dim3(64, NIMG), 256>>>();
  dim3 gsamp((NP + 127) / 128, NIMG);
  k_sample<<<gsamp, 128>>>(P, inputs, targets, images);
  k_loss<<<gsamp, 128>>>();
  k_final<<<1, 1>>>(out, out_size);
}